// round 11
// baseline (speedup 1.0000x reference)
#include <cuda_runtime.h>
#include <cuda_bf16.h>
#include <math.h>
#include <stdint.h>

#define EMBX 300
#define EMBP 320
#define HX 512
#define HHX 256
#define BX 128
#define LX 128
#define NX (BX*LX)          /* 16384 */
#define SX 10
#define LAYERSX 7
#define K_SAGE 1024

#define SZ_HID (NX*2*HX)
#define OFF_GE SZ_HID
#define OFF_OV (SZ_HID + 2*BX*HX)

// ---------------- scratch (device globals) ----------------
__device__ __align__(16) __nv_bfloat16 g_embh[(size_t)NX*EMBP];
__device__ __align__(16) __nv_bfloat16 g_embl[(size_t)NX*EMBP];
__device__ __align__(16) __nv_bfloat16 g_wihh[2][(size_t)1024*EMBP];
__device__ __align__(16) __nv_bfloat16 g_wihl[2][(size_t)1024*EMBP];
__device__ __align__(16) __nv_bfloat16 g_wh[2][LAYERSX][(size_t)HX*K_SAGE];
__device__ __align__(16) __nv_bfloat16 g_wl[2][LAYERSX][(size_t)HX*K_SAGE];
__device__ __align__(16) __nv_bfloat16 g_cath[2][(size_t)NX*K_SAGE];
__device__ __align__(16) __nv_bfloat16 g_catl[2][(size_t)NX*K_SAGE];
__device__ __align__(16) float g_xp[2][(size_t)NX*1024];
__device__ __align__(16) float g_nrep[(size_t)(NX+1)*HX];
__device__ __align__(16) float g_hid[2][2][(size_t)(NX+1)*HX];
__device__ __align__(16) float g_len[2][NX];
__device__ __align__(16) float g_bias[2][1024];
__device__ __align__(16) float g_sbias[2][LAYERSX*HX];
__device__ __align__(16) float g_whhq[2][HHX*HHX*4];

// ---------------- helpers ----------------
#define SWZ(o) ((o) ^ (((o) >> 3) & 0x70))

__device__ __forceinline__ uint32_t s2u(const void* p) {
    uint32_t a;
    asm("{ .reg .u64 t; cvta.to.shared.u64 t, %1; cvt.u32.u64 %0, t; }"
        : "=r"(a) : "l"(p));
    return a;
}
__device__ __forceinline__ void cpa16(uint32_t d, const void* g) {
    asm volatile("cp.async.cg.shared.global [%0], [%1], 16;" :: "r"(d), "l"(g));
}
__device__ __forceinline__ void ldsm4(uint32_t* r, uint32_t addr) {
    asm volatile("ldmatrix.sync.aligned.m8n8.x4.shared.b16 {%0,%1,%2,%3}, [%4];"
        : "=r"(r[0]), "=r"(r[1]), "=r"(r[2]), "=r"(r[3]) : "r"(addr));
}
__device__ __forceinline__ void mma16816(float* d, const uint32_t* a, const uint32_t* b) {
    asm volatile("mma.sync.aligned.m16n8k16.row.col.f32.bf16.bf16.f32 "
        "{%0,%1,%2,%3}, {%4,%5,%6,%7}, {%8,%9}, {%0,%1,%2,%3};"
        : "+f"(d[0]), "+f"(d[1]), "+f"(d[2]), "+f"(d[3])
        : "r"(a[0]), "r"(a[1]), "r"(a[2]), "r"(a[3]), "r"(b[0]), "r"(b[1]));
}
__device__ __forceinline__ void bsplit(float a, __nv_bfloat16& h, __nv_bfloat16& l) {
    h = __float2bfloat16(a);
    l = __float2bfloat16(a - __bfloat162float(h));
}
__device__ __forceinline__ float fsig(float x) {
    return __fdividef(1.f, 1.f + __expf(-x));
}
__device__ __forceinline__ float ftanh(float x) {
    float e = __expf(-2.f*x);
    return __fdividef(1.f - e, 1.f + e);
}

// ---------------- embedding lookup -> bf16 hi/lo, K padded to 320 ----------
__global__ void k_embed(const int* __restrict__ feat, const float* __restrict__ Wemb)
{
    int idx = blockIdx.x * blockDim.x + threadIdx.x;
    if (idx >= NX*EMBP) return;
    int n = idx / EMBP, e = idx - n*EMBP;
    float v = 0.f;
    if (e < EMBX) v = Wemb[(size_t)feat[n]*EMBX + e];
    __nv_bfloat16 h, l; bsplit(v, h, l);
    g_embh[idx] = h; g_embl[idx] = l;
}

// ---------------- bias precompute: bih+bhh, packed SAGE biases -------------
__global__ void k_bias(const float* bihf, const float* bhhf,
                       const float* bihb, const float* bhhb,
                       const float* fwb, const float* bwb)
{
    int j = blockIdx.x * blockDim.x + threadIdx.x;
    if (j < 4*HHX) {
        g_bias[0][j] = bihf[j] + bhhf[j];
        g_bias[1][j] = bihb[j] + bhhb[j];
    }
    if (j < LAYERSX*HX) {
        g_sbias[0][j] = fwb[j];
        g_sbias[1][j] = bwb[j];
    }
}

// ---------------- Wih split -> bf16 hi/lo, padded to 320 -------------------
__global__ void k_split_wih(const float* __restrict__ Wf, const float* __restrict__ Wb)
{
    int idx = blockIdx.x * blockDim.x + threadIdx.x;
    if (idx >= 2*1024*EMBP) return;
    int d = idx / (1024*EMBP);
    int rem = idx - d*(1024*EMBP);
    int r = rem / EMBP, e = rem - r*EMBP;
    const float* W = d ? Wb : Wf;
    float v = (e < EMBX) ? W[(size_t)r*EMBX + e] : 0.f;
    __nv_bfloat16 h, l; bsplit(v, h, l);
    g_wihh[d][rem] = h; g_wihl[d][rem] = l;
}

// ---------------- SAGE W split -> bf16 hi/lo -------------------------------
__global__ void k_split_sagew(const float* __restrict__ Wf, const float* __restrict__ Wb)
{
    const int per = LAYERSX*HX*K_SAGE;
    int idx = blockIdx.x * blockDim.x + threadIdx.x;
    if (idx >= 2*per) return;
    int d = idx / per, rem = idx - d*per;
    float v = (d ? Wb : Wf)[rem];
    __nv_bfloat16 h, l; bsplit(v, h, l);
    (&g_wh[0][0][0])[(size_t)d*per + rem] = h;
    (&g_wl[0][0][0])[(size_t)d*per + rem] = l;
}

// ---------------- Whh transpose into [k][j][{i,f,g,o}] float4 layout --------
__global__ void k_whhq(const float* __restrict__ Wf, const float* __restrict__ Wb)
{
    int idx = blockIdx.x * blockDim.x + threadIdx.x;
    if (idx >= 2*HHX*HHX) return;
    int d = idx / (HHX*HHX);
    int rem = idx - d*(HHX*HHX);
    int k = rem / HHX, j = rem - k*HHX;
    const float* W = d ? Wb : Wf;
    float4 v;
    v.x = W[(size_t)(0*HHX + j)*HHX + k];
    v.y = W[(size_t)(1*HHX + j)*HHX + k];
    v.z = W[(size_t)(2*HHX + j)*HHX + k];
    v.w = W[(size_t)(3*HHX + j)*HHX + k];
    *(float4*)&g_whhq[d][(size_t)rem*4] = v;
}

// ============ mma.sync bf16x3 GEMM, dual-direction via blockIdx.z ==========
__device__ __forceinline__ void load_stage(
    uint32_t sb, int s, int kc,
    const char* A0, const char* A1, const char* B0, const char* B1,
    int K, int tid)
{
    const char* srcs[4] = { A0, A1, B0, B1 };
    uint32_t stb = sb + s*65536;
#pragma unroll
    for (int t4 = 0; t4 < 4; t4++) {
        const char* src = srcs[t4] + (size_t)kc*128;
        uint32_t tb = stb + t4*16384;
#pragma unroll
        for (int i = 0; i < 4; i++) {
            int q = tid + i*256;
            int r = q >> 3, sc = q & 7;
            cpa16(tb + SWZ(r*128 + sc*16), src + (size_t)r*(size_t)K*2 + sc*16);
        }
    }
    asm volatile("cp.async.commit_group;" ::: "memory");
}

__global__ __launch_bounds__(256, 1) void k_mma_gemm(
    const __nv_bfloat16* __restrict__ Ah, const __nv_bfloat16* __restrict__ Al,
    const __nv_bfloat16* __restrict__ Bh, const __nv_bfloat16* __restrict__ Bl,
    const float* __restrict__ bias, float* __restrict__ C,
    int Ncols, int K, int relu,
    size_t sA, size_t sB, size_t sBias, size_t sC)
{
    extern __shared__ char dsm[];
    const int z = blockIdx.z;
    Ah += (size_t)z*sA;  Al += (size_t)z*sA;
    Bh += (size_t)z*sB;  Bl += (size_t)z*sB;
    bias += (size_t)z*sBias;
    C  += (size_t)z*sC;

    const int tid = threadIdx.x;
    const int wid = tid >> 5, lane = tid & 31;
    const int row0 = blockIdx.y << 7;
    const int col0 = blockIdx.x << 7;
    const int nch = K >> 6;

    uint32_t sb = s2u(dsm);
    sb = (sb + 1023u) & ~1023u;

    const char* A0 = (const char*)(Ah + (size_t)row0*K);
    const char* A1 = (const char*)(Al + (size_t)row0*K);
    const char* B0 = (const char*)(Bh + (size_t)col0*K);
    const char* B1 = (const char*)(Bl + (size_t)col0*K);

    const int wm = (wid >> 1) * 32;
    const int wn = (wid & 1) * 64;
    const int gq8 = lane >> 3, lr = lane & 7;
    const int a_row = wm + lr + ((gq8 & 1) << 3);
    const int a_cb  = (gq8 >> 1) << 4;
    const int b_row = wn + lr + ((gq8 >> 1) << 3);
    const int b_cb  = (gq8 & 1) << 4;

    float acc[2][8][4];
#pragma unroll
    for (int mt = 0; mt < 2; mt++)
#pragma unroll
        for (int nt = 0; nt < 8; nt++)
#pragma unroll
            for (int j = 0; j < 4; j++) acc[mt][nt][j] = 0.f;

    load_stage(sb, 0, 0, A0, A1, B0, B1, K, tid);
    if (nch > 1) load_stage(sb, 1, 1, A0, A1, B0, B1, K, tid);

    int sidx = 0;
    for (int kc = 0; kc < nch; kc++) {
        if (kc + 1 < nch)
            asm volatile("cp.async.wait_group 1;" ::: "memory");
        else
            asm volatile("cp.async.wait_group 0;" ::: "memory");
        __syncthreads();
        if (kc + 2 < nch) {
            int ls = sidx + 2; if (ls >= 3) ls -= 3;
            load_stage(sb, ls, kc + 2, A0, A1, B0, B1, K, tid);
        }
        const uint32_t stb = sb + sidx*65536;
#pragma unroll
        for (int ks = 0; ks < 4; ks++) {
            const int k0b = ks * 32;
            uint32_t ah[2][4], al[2][4];
#pragma unroll
            for (int mt = 0; mt < 2; mt++) {
                uint32_t off = SWZ((uint32_t)((a_row + mt*16)*128 + (a_cb + k0b)));
                ldsm4(ah[mt], stb + off);
                ldsm4(al[mt], stb + 16384 + off);
            }
            uint32_t bh[4][4], bl[4][4];
#pragma unroll
            for (int gg = 0; gg < 4; gg++) {
                uint32_t off = SWZ((uint32_t)((b_row + gg*16)*128 + (b_cb + k0b)));
                ldsm4(bh[gg], stb + 32768 + off);
                ldsm4(bl[gg], stb + 49152 + off);
            }
#pragma unroll
            for (int mt = 0; mt < 2; mt++)
#pragma unroll
                for (int nt = 0; nt < 8; nt++) {
                    const uint32_t* bhp = &bh[nt >> 1][(nt & 1) * 2];
                    const uint32_t* blp = &bl[nt >> 1][(nt & 1) * 2];
                    mma16816(acc[mt][nt], ah[mt], bhp);
                    mma16816(acc[mt][nt], ah[mt], blp);
                    mma16816(acc[mt][nt], al[mt], bhp);
                }
        }
        sidx++; if (sidx >= 3) sidx = 0;
    }

    const int erow = row0 + wm + (lane >> 2);
    const int ecol = col0 + wn + 2*(lane & 3);
#pragma unroll
    for (int mt = 0; mt < 2; mt++)
#pragma unroll
        for (int nt = 0; nt < 8; nt++) {
            int r = erow + mt*16;
            int cc = ecol + nt*8;
            float2 v0, v1;
            v0.x = acc[mt][nt][0] + bias[cc];
            v0.y = acc[mt][nt][1] + bias[cc+1];
            v1.x = acc[mt][nt][2] + bias[cc];
            v1.y = acc[mt][nt][3] + bias[cc+1];
            if (relu) {
                v0.x = fmaxf(v0.x, 0.f); v0.y = fmaxf(v0.y, 0.f);
                v1.x = fmaxf(v1.x, 0.f); v1.y = fmaxf(v1.y, 0.f);
            }
            *(float2*)&C[(size_t)r*Ncols + cc]     = v0;
            *(float2*)&C[(size_t)(r+8)*Ncols + cc] = v1;
        }
}

// ----- persistent BiLSTM v3: cluster(2) j-split + intra-block k-split ------
// 128 blocks x 256 threads. block = (dir, rowgroup, j-half). Threads:
// jloc = tid&127 (gate column within half), kg = tid>>7 (k-half).
// 2 warps/SMSP on 128 SMs -> issue 8192 cyc/step, L2-bound ~10.2k.
__global__ __launch_bounds__(256) __cluster_dims__(2, 1, 1) void k_lstm3()
{
    const int bx = blockIdx.x;
    const int pair = bx >> 1;       // 0..63
    const int jh  = bx & 1;         // my j-half (== cluster rank)
    const int dir = pair >> 5;
    const int rg  = pair & 31;
    const int tid = threadIdx.x;
    const int jloc = tid & 127;
    const int kg   = tid >> 7;      // k-half 0/1
    const int jg   = jh*128 + jloc; // gate column 0..255
    const float* __restrict__ Wq = g_whhq[dir];
    const float* __restrict__ xp = g_xp[dir];

    __shared__ __align__(16) float hbuf[2][HHX][4];   // [pp][k][row], full h
    __shared__ __align__(16) float red[128][4][4];    // kg1 partials [jloc][gate][row]
    *(float4*)&hbuf[0][tid][0] = make_float4(0.f, 0.f, 0.f, 0.f);
    if (tid < 256 - HHX) { /* HHX==256: nothing extra */ }
    float c[4] = {0.f, 0.f, 0.f, 0.f};

    const uint32_t locBase = s2u(&hbuf[0][0][0]);
    uint32_t remBase;
    asm("mapa.shared::cluster.u32 %0, %1, %2;"
        : "=r"(remBase) : "r"(locBase), "r"(jh ^ 1));
    __syncthreads();

    int p = 0;
    const int k0 = kg*128;
    for (int t = 0; t < LX; t++) {
        const int tseq = dir ? (LX - 1 - t) : t;
        // prefetch xp rows for this step (used by kg0 after the k-loop)
        float xpre[4][4];
        if (kg == 0) {
#pragma unroll
            for (int r = 0; r < 4; r++) {
                const float* xr = xp + ((size_t)(rg*4 + r)*LX + tseq)*(4*HHX);
                xpre[r][0] = xr[jg];
                xpre[r][1] = xr[HHX + jg];
                xpre[r][2] = xr[2*HHX + jg];
                xpre[r][3] = xr[3*HHX + jg];
            }
        }
        float a0[4] = {0,0,0,0}, a1[4] = {0,0,0,0};
        float a2[4] = {0,0,0,0}, a3[4] = {0,0,0,0};
#pragma unroll 8
        for (int kk = 0; kk < 128; kk++) {
            const int k = k0 + kk;
            float4 w  = *(const float4*)&Wq[((size_t)k*HHX + jg)*4];
            float4 h4 = *(const float4*)&hbuf[p][k][0];
            a0[0] = fmaf(w.x, h4.x, a0[0]); a1[0] = fmaf(w.y, h4.x, a1[0]);
            a2[0] = fmaf(w.z, h4.x, a2[0]); a3[0] = fmaf(w.w, h4.x, a3[0]);
            a0[1] = fmaf(w.x, h4.y, a0[1]); a1[1] = fmaf(w.y, h4.y, a1[1]);
            a2[1] = fmaf(w.z, h4.y, a2[1]); a3[1] = fmaf(w.w, h4.y, a3[1]);
            a0[2] = fmaf(w.x, h4.z, a0[2]); a1[2] = fmaf(w.y, h4.z, a1[2]);
            a2[2] = fmaf(w.z, h4.z, a2[2]); a3[2] = fmaf(w.w, h4.z, a3[2]);
            a0[3] = fmaf(w.x, h4.w, a0[3]); a1[3] = fmaf(w.y, h4.w, a1[3]);
            a2[3] = fmaf(w.z, h4.w, a2[3]); a3[3] = fmaf(w.w, h4.w, a3[3]);
        }
        if (kg == 1) {
            *(float4*)&red[jloc][0][0] = make_float4(a0[0], a0[1], a0[2], a0[3]);
            *(float4*)&red[jloc][1][0] = make_float4(a1[0], a1[1], a1[2], a1[3]);
            *(float4*)&red[jloc][2][0] = make_float4(a2[0], a2[1], a2[2], a2[3]);
            *(float4*)&red[jloc][3][0] = make_float4(a3[0], a3[1], a3[2], a3[3]);
        }
        __syncthreads();
        if (kg == 0) {
            float4 o0 = *(float4*)&red[jloc][0][0];
            float4 o1 = *(float4*)&red[jloc][1][0];
            float4 o2 = *(float4*)&red[jloc][2][0];
            float4 o3 = *(float4*)&red[jloc][3][0];
            a0[0] += o0.x; a0[1] += o0.y; a0[2] += o0.z; a0[3] += o0.w;
            a1[0] += o1.x; a1[1] += o1.y; a1[2] += o1.z; a1[3] += o1.w;
            a2[0] += o2.x; a2[1] += o2.y; a2[2] += o2.z; a2[3] += o2.w;
            a3[0] += o3.x; a3[1] += o3.y; a3[2] += o3.z; a3[3] += o3.w;
            float hv[4];
#pragma unroll
            for (int r = 0; r < 4; r++) {
                const int row = rg*4 + r;
                const size_t nidx = (size_t)row*LX + tseq;
                float gi = a0[r] + xpre[r][0];
                float gf = a1[r] + xpre[r][1];
                float gg = a2[r] + xpre[r][2];
                float go = a3[r] + xpre[r][3];
                float si = fsig(gi), sf = fsig(gf), so = fsig(go);
                float tg = ftanh(gg);
                c[r] = sf*c[r] + si*tg;
                hv[r] = so * ftanh(c[r]);
                g_nrep[nidx*HX + (size_t)dir*HHX + jg] = hv[r];
            }
            *(float4*)&hbuf[p ^ 1][jg][0] = make_float4(hv[0], hv[1], hv[2], hv[3]);
            uint32_t ra = remBase + (uint32_t)(((p ^ 1)*HHX + jg)*4) * 4u;
            asm volatile("st.shared::cluster.f32 [%0],    %1;" :: "r"(ra), "f"(hv[0]));
            asm volatile("st.shared::cluster.f32 [%0+4],  %1;" :: "r"(ra), "f"(hv[1]));
            asm volatile("st.shared::cluster.f32 [%0+8],  %1;" :: "r"(ra), "f"(hv[2]));
            asm volatile("st.shared::cluster.f32 [%0+12], %1;" :: "r"(ra), "f"(hv[3]));
        }
        asm volatile("barrier.cluster.arrive.aligned;" ::: "memory");
        asm volatile("barrier.cluster.wait.aligned;" ::: "memory");
        p ^= 1;
    }
}

// ---------------- padding row + zero row N of hidden buffers ----------------
__global__ void k_pad_zero(const float* __restrict__ pad)
{
    int j = threadIdx.x;
    if (j < HX) {
        g_nrep[(size_t)NX*HX + j] = pad[j];
        g_hid[0][0][(size_t)NX*HX + j] = 0.f;
        g_hid[0][1][(size_t)NX*HX + j] = 0.f;
        g_hid[1][0][(size_t)NX*HX + j] = 0.f;
        g_hid[1][1][(size_t)NX*HX + j] = 0.f;
    }
}

// ---------------- initial hidden = node_repres[batch_nodes] ----------------
__global__ void k_init_hid(const int* __restrict__ nodes)
{
    int idx = blockIdx.x * blockDim.x + threadIdx.x;
    if (idx >= NX*HX) return;
    int n = idx >> 9, cc = idx & (HX - 1);
    float v = g_nrep[(size_t)nodes[n]*HX + cc];
    g_hid[0][0][idx] = v;
    g_hid[1][0][idx] = v;
}

// ------- gather + mean + concat -> bf16 hi/lo cat; optional len compute ----
__global__ __launch_bounds__(128) void k_gm(
    const float* __restrict__ selfT, size_t sSelf,
    const float* __restrict__ neighT, size_t sNeigh,
    const int* __restrict__ nodes,
    const int* __restrict__ adjF, const int* __restrict__ adjB,
    int computeLen)
{
    const int n = blockIdx.x;
    const int dir = blockIdx.y;
    selfT  += (size_t)dir*sSelf;
    neighT += (size_t)dir*sNeigh;
    const int* adj = dir ? adjB : adjF;
    __nv_bfloat16* cath = g_cath[dir];
    __nv_bfloat16* catl = g_catl[dir];

    const int t = threadIdx.x;
    __shared__ int nb[SX];
    __shared__ float s_red[4][SX];
    __shared__ float s_inv;
    if (t < SX) nb[t] = adj[(size_t)nodes[n]*SX + t];
    if (!computeLen && t == 0) s_inv = 1.f / g_len[dir][n];
    __syncthreads();

    const int c = t * 4;
    float4 s = {0.f, 0.f, 0.f, 0.f};
    float rq[SX];
#pragma unroll
    for (int q = 0; q < SX; q++) {
        const float4 v = *(const float4*)&neighT[(size_t)nb[q]*HX + c];
        s.x += v.x; s.y += v.y; s.z += v.z; s.w += v.w;
        if (computeLen) {
            rq[q] = fmaxf(v.x, 0.f) + fmaxf(v.y, 0.f)
                  + fmaxf(v.z, 0.f) + fmaxf(v.w, 0.f);
        }
    }
    if (computeLen) {
        const int lane = t & 31, w = t >> 5;
#pragma unroll
        for (int q = 0; q < SX; q++) {
            float x = rq[q];
#pragma unroll
            for (int o = 16; o; o >>= 1) x += __shfl_xor_sync(0xffffffffu, x, o);
            if (lane == 0) s_red[w][q] = x;
        }
        __syncthreads();
        if (t == 0) {
            float cnt = 0.f;
#pragma unroll
            for (int q = 0; q < SX; q++) {
                float tot = s_red[0][q] + s_red[1][q] + s_red[2][q] + s_red[3][q];
                if (tot > 0.f) cnt += 1.f;
            }
            g_len[dir][n] = cnt;
            s_inv = 1.f / cnt;
        }
        __syncthreads();
    }
    const float invlen = s_inv;

    float4 sv = *(const float4*)&selfT[(size_t)n*HX + c];
    float4 m = {s.x*invlen, s.y*invlen, s.z*invlen, s.w*invlen};

    size_t o = (size_t)n*K_SAGE + c;
    __nv_bfloat16 h0,l0,h1,l1,h2,l2,h3,l3;
    bsplit(sv.x,h0,l0); bsplit(sv.y,h1,l1); bsplit(sv.z,h2,l2); bsplit(sv.w,h3,l3);
    *(__nv_bfloat162*)&cath[o]   = __halves2bfloat162(h0,h1);
    *(__nv_bfloat162*)&cath[o+2] = __halves2bfloat162(h2,h3);
    *(__nv_bfloat162*)&catl[o]   = __halves2bfloat162(l0,l1);
    *(__nv_bfloat162*)&catl[o+2] = __halves2bfloat162(l2,l3);

    bsplit(m.x,h0,l0); bsplit(m.y,h1,l1); bsplit(m.z,h2,l2); bsplit(m.w,h3,l3);
    *(__nv_bfloat162*)&cath[o+HX]   = __halves2bfloat162(h0,h1);
    *(__nv_bfloat162*)&cath[o+HX+2] = __halves2bfloat162(h2,h3);
    *(__nv_bfloat162*)&catl[o+HX]   = __halves2bfloat162(l0,l1);
    *(__nv_bfloat162*)&catl[o+HX+2] = __halves2bfloat162(l2,l3);
}

// ---------------- finalize + pool ----------------
__global__ void k_finalize(float* __restrict__ out, int fin)
{
    int idx = blockIdx.x * blockDim.x + threadIdx.x;
    if (idx >= NX*HX) return;
    int n = idx >> 9, cc = idx & (HX - 1);
    out[(size_t)n*1024 + cc]       = g_hid[0][fin][idx];
    out[(size_t)n*1024 + 512 + cc] = g_hid[1][fin][idx];
    out[(size_t)OFF_OV + idx]      = g_nrep[idx];
}

__global__ void k_pool(const float* __restrict__ hid, float* __restrict__ ge)
{
    const int b = blockIdx.x;
    const int jx = threadIdx.x;
    float m = -3.402823466e38f;
    const float* base = hid + (size_t)b*LX*1024 + jx;
    for (int l = 0; l < LX; l++) m = fmaxf(m, base[(size_t)l*1024]);
    ge[(size_t)b*1024 + jx] = m;
}

// ============================ host launcher ================================
extern "C" void kernel_launch(void* const* d_in, const int* in_sizes, int n_in,
                              void* d_out, int out_size)
{
    const int*   feature_info = (const int*)d_in[0];
    const int*   batch_nodes  = (const int*)d_in[1];
    const int*   fw_adj       = (const int*)d_in[2];
    const int*   bw_adj       = (const int*)d_in[3];
    const float* W_emb        = (const float*)d_in[4];
    const float* Wih_f        = (const float*)d_in[5];
    const float* Whh_f        = (const float*)d_in[6];
    const float* bih_f        = (const float*)d_in[7];
    const float* bhh_f        = (const float*)d_in[8];
    const float* Wih_b        = (const float*)d_in[9];
    const float* Whh_b        = (const float*)d_in[10];
    const float* bih_b        = (const float*)d_in[11];
    const float* bhh_b        = (const float*)d_in[12];
    const float* padding_vec  = (const float*)d_in[13];
    const float* fw_W         = (const float*)d_in[14];
    const float* fw_b         = (const float*)d_in[15];
    const float* bw_W         = (const float*)d_in[16];
    const float* bw_b         = (const float*)d_in[17];
    float* out = (float*)d_out;

    const int DSMEM = 3*65536 + 1024;
    cudaFuncSetAttribute(k_mma_gemm, cudaFuncAttributeMaxDynamicSharedMemorySize, DSMEM);

    float *p_nrep, *p_hid, *p_bias, *p_sbias, *p_xp;
    __nv_bfloat16 *p_embh, *p_embl, *p_wihh, *p_wihl, *p_wh, *p_wl, *p_cath, *p_catl;
    cudaGetSymbolAddress((void**)&p_nrep, g_nrep);
    cudaGetSymbolAddress((void**)&p_hid,  g_hid);
    cudaGetSymbolAddress((void**)&p_bias, g_bias);
    cudaGetSymbolAddress((void**)&p_sbias,g_sbias);
    cudaGetSymbolAddress((void**)&p_xp,   g_xp);
    cudaGetSymbolAddress((void**)&p_embh, g_embh);
    cudaGetSymbolAddress((void**)&p_embl, g_embl);
    cudaGetSymbolAddress((void**)&p_wihh, g_wihh);
    cudaGetSymbolAddress((void**)&p_wihl, g_wihl);
    cudaGetSymbolAddress((void**)&p_wh,   g_wh);
    cudaGetSymbolAddress((void**)&p_wl,   g_wl);
    cudaGetSymbolAddress((void**)&p_cath, g_cath);
    cudaGetSymbolAddress((void**)&p_catl, g_catl);

    const size_t HIDQ = (size_t)(NX+1)*HX;
    const size_t HIDD = 2*HIDQ;
    float* hid_d[2][2];
    for (int d = 0; d < 2; d++)
        for (int q = 0; q < 2; q++)
            hid_d[d][q] = p_hid + ((size_t)d*2 + q)*HIDQ;

    // 1. embed + weight preprocessing
    k_embed<<<(NX*EMBP + 255)/256, 256>>>(feature_info, W_emb);
    k_bias<<<(LAYERSX*HX + 255)/256, 256>>>(bih_f, bhh_f, bih_b, bhh_b, fw_b, bw_b);
    k_split_wih<<<(2*1024*EMBP + 255)/256, 256>>>(Wih_f, Wih_b);
    k_split_sagew<<<(2*LAYERSX*HX*K_SAGE + 255)/256, 256>>>(fw_W, bw_W);
    k_whhq<<<(2*HHX*HHX + 255)/256, 256>>>(Whh_f, Whh_b);

    // 2. input projections, both dirs in one launch (bf16x3 mma)
    dim3 gxp(1024/128, NX/128, 2);
    k_mma_gemm<<<gxp, 256, DSMEM>>>(p_embh, p_embl, p_wihh, p_wihl,
                                    p_bias, p_xp, 1024, EMBP, 0,
                                    0, (size_t)1024*EMBP, 1024, (size_t)NX*1024);

    // 3. persistent BiLSTM (cluster j-split + intra-block k-split)
    k_lstm3<<<128, 256>>>();

    // 4. padding row / zero rows / init hidden
    k_pad_zero<<<1, 512>>>(padding_vec);
    k_init_hid<<<(NX*HX + 255)/256, 256>>>(batch_nodes);

    // 5. 7 SAGE layers, both dirs per launch; layer 0 fuses len computation
    int pin = 0;
    dim3 ggm(NX, 2);
    dim3 gsage(HX/128, NX/128, 2);
    for (int l = 0; l < LAYERSX; l++) {
        if (l == 0)
            k_gm<<<ggm, 128>>>(hid_d[0][pin], HIDD, p_nrep, 0,
                               batch_nodes, fw_adj, bw_adj, 1);
        else
            k_gm<<<ggm, 128>>>(hid_d[0][pin], HIDD, hid_d[0][pin], HIDD,
                               batch_nodes, fw_adj, bw_adj, 0);
        k_mma_gemm<<<gsage, 256, DSMEM>>>(
            p_cath, p_catl,
            p_wh + (size_t)l*HX*K_SAGE, p_wl + (size_t)l*HX*K_SAGE,
            p_sbias + (size_t)l*HX, hid_d[0][1 - pin],
            HX, K_SAGE, 1,
            (size_t)NX*K_SAGE, (size_t)LAYERSX*HX*K_SAGE,
            (size_t)LAYERSX*HX, HIDD);
        pin ^= 1;
    }

    // 6. outputs
    k_finalize<<<(NX*HX + 255)/256, 256>>>(out, pin);
    k_pool<<<BX, 1024>>>(out, out + OFF_GE);
    (void)in_sizes; (void)n_in; (void)out_size;
}

// round 12
// speedup vs baseline: 1.2479x; 1.2479x over previous
#include <cuda_runtime.h>
#include <cuda_bf16.h>
#include <math.h>
#include <stdint.h>

#define EMBX 300
#define EMBP 320
#define HX 512
#define HHX 256
#define BX 128
#define LX 128
#define NX (BX*LX)          /* 16384 */
#define SX 10
#define LAYERSX 7
#define K_SAGE 1024

#define SZ_HID (NX*2*HX)
#define OFF_GE SZ_HID
#define OFF_OV (SZ_HID + 2*BX*HX)

// ---------------- scratch (device globals) ----------------
__device__ __align__(16) __nv_bfloat16 g_embh[(size_t)NX*EMBP];
__device__ __align__(16) __nv_bfloat16 g_embl[(size_t)NX*EMBP];
__device__ __align__(16) __nv_bfloat16 g_wihh[2][(size_t)1024*EMBP];
__device__ __align__(16) __nv_bfloat16 g_wihl[2][(size_t)1024*EMBP];
__device__ __align__(16) __nv_bfloat16 g_wh[2][LAYERSX][(size_t)HX*K_SAGE];
__device__ __align__(16) __nv_bfloat16 g_wl[2][LAYERSX][(size_t)HX*K_SAGE];
// ping-pong cat matrices: [pp][dir][(N+1) rows x 1024]; self cols 0-511, mean 512-1023
__device__ __align__(16) __nv_bfloat16 g_cath[2][2][(size_t)(NX+1)*K_SAGE];
__device__ __align__(16) __nv_bfloat16 g_catl[2][2][(size_t)(NX+1)*K_SAGE];
__device__ __align__(16) float g_xp[2][(size_t)NX*1024];
__device__ __align__(16) float g_nrep[(size_t)(NX+1)*HX];
__device__ __align__(16) float g_len[2][NX];
__device__ __align__(16) float g_bias[2][1024];
__device__ __align__(16) float g_sbias[2][LAYERSX*HX];
__device__ __align__(16) float g_whhq[2][HHX*HHX*4];

// ---------------- helpers ----------------
#define SWZ(o) ((o) ^ (((o) >> 3) & 0x70))

__device__ __forceinline__ uint32_t s2u(const void* p) {
    uint32_t a;
    asm("{ .reg .u64 t; cvta.to.shared.u64 t, %1; cvt.u32.u64 %0, t; }"
        : "=r"(a) : "l"(p));
    return a;
}
__device__ __forceinline__ void cpa16(uint32_t d, const void* g) {
    asm volatile("cp.async.cg.shared.global [%0], [%1], 16;" :: "r"(d), "l"(g));
}
__device__ __forceinline__ void ldsm4(uint32_t* r, uint32_t addr) {
    asm volatile("ldmatrix.sync.aligned.m8n8.x4.shared.b16 {%0,%1,%2,%3}, [%4];"
        : "=r"(r[0]), "=r"(r[1]), "=r"(r[2]), "=r"(r[3]) : "r"(addr));
}
__device__ __forceinline__ void mma16816(float* d, const uint32_t* a, const uint32_t* b) {
    asm volatile("mma.sync.aligned.m16n8k16.row.col.f32.bf16.bf16.f32 "
        "{%0,%1,%2,%3}, {%4,%5,%6,%7}, {%8,%9}, {%0,%1,%2,%3};"
        : "+f"(d[0]), "+f"(d[1]), "+f"(d[2]), "+f"(d[3])
        : "r"(a[0]), "r"(a[1]), "r"(a[2]), "r"(a[3]), "r"(b[0]), "r"(b[1]));
}
__device__ __forceinline__ void bsplit(float a, __nv_bfloat16& h, __nv_bfloat16& l) {
    h = __float2bfloat16(a);
    l = __float2bfloat16(a - __bfloat162float(h));
}
__device__ __forceinline__ float fsig(float x) {
    return __fdividef(1.f, 1.f + __expf(-x));
}
__device__ __forceinline__ float ftanh(float x) {
    float e = __expf(-2.f*x);
    return __fdividef(1.f - e, 1.f + e);
}
__device__ __forceinline__ float b2f(__nv_bfloat16 v) { return __bfloat162float(v); }

// ---------------- embedding lookup -> bf16 hi/lo, K padded to 320 ----------
__global__ void k_embed(const int* __restrict__ feat, const float* __restrict__ Wemb)
{
    int idx = blockIdx.x * blockDim.x + threadIdx.x;
    if (idx >= NX*EMBP) return;
    int n = idx / EMBP, e = idx - n*EMBP;
    float v = 0.f;
    if (e < EMBX) v = Wemb[(size_t)feat[n]*EMBX + e];
    __nv_bfloat16 h, l; bsplit(v, h, l);
    g_embh[idx] = h; g_embl[idx] = l;
}

// ---------------- bias precompute: bih+bhh, packed SAGE biases -------------
__global__ void k_bias(const float* bihf, const float* bhhf,
                       const float* bihb, const float* bhhb,
                       const float* fwb, const float* bwb)
{
    int j = blockIdx.x * blockDim.x + threadIdx.x;
    if (j < 4*HHX) {
        g_bias[0][j] = bihf[j] + bhhf[j];
        g_bias[1][j] = bihb[j] + bhhb[j];
    }
    if (j < LAYERSX*HX) {
        g_sbias[0][j] = fwb[j];
        g_sbias[1][j] = bwb[j];
    }
}

// ---------------- Wih split -> bf16 hi/lo, padded to 320 -------------------
__global__ void k_split_wih(const float* __restrict__ Wf, const float* __restrict__ Wb)
{
    int idx = blockIdx.x * blockDim.x + threadIdx.x;
    if (idx >= 2*1024*EMBP) return;
    int d = idx / (1024*EMBP);
    int rem = idx - d*(1024*EMBP);
    int r = rem / EMBP, e = rem - r*EMBP;
    const float* W = d ? Wb : Wf;
    float v = (e < EMBX) ? W[(size_t)r*EMBX + e] : 0.f;
    __nv_bfloat16 h, l; bsplit(v, h, l);
    g_wihh[d][rem] = h; g_wihl[d][rem] = l;
}

// ---------------- SAGE W split -> bf16 hi/lo -------------------------------
__global__ void k_split_sagew(const float* __restrict__ Wf, const float* __restrict__ Wb)
{
    const int per = LAYERSX*HX*K_SAGE;
    int idx = blockIdx.x * blockDim.x + threadIdx.x;
    if (idx >= 2*per) return;
    int d = idx / per, rem = idx - d*per;
    float v = (d ? Wb : Wf)[rem];
    __nv_bfloat16 h, l; bsplit(v, h, l);
    (&g_wh[0][0][0])[(size_t)d*per + rem] = h;
    (&g_wl[0][0][0])[(size_t)d*per + rem] = l;
}

// ---------------- Whh transpose into [k][j][{i,f,g,o}] float4 layout --------
__global__ void k_whhq(const float* __restrict__ Wf, const float* __restrict__ Wb)
{
    int idx = blockIdx.x * blockDim.x + threadIdx.x;
    if (idx >= 2*HHX*HHX) return;
    int d = idx / (HHX*HHX);
    int rem = idx - d*(HHX*HHX);
    int k = rem / HHX, j = rem - k*HHX;
    const float* W = d ? Wb : Wf;
    float4 v;
    v.x = W[(size_t)(0*HHX + j)*HHX + k];
    v.y = W[(size_t)(1*HHX + j)*HHX + k];
    v.z = W[(size_t)(2*HHX + j)*HHX + k];
    v.w = W[(size_t)(3*HHX + j)*HHX + k];
    *(float4*)&g_whhq[d][(size_t)rem*4] = v;
}

// ============ mma.sync bf16x3 GEMM, dual-direction via blockIdx.z ==========
__device__ __forceinline__ void load_stage(
    uint32_t sb, int s, int kc,
    const char* A0, const char* A1, const char* B0, const char* B1,
    int K, int tid)
{
    const char* srcs[4] = { A0, A1, B0, B1 };
    uint32_t stb = sb + s*65536;
#pragma unroll
    for (int t4 = 0; t4 < 4; t4++) {
        const char* src = srcs[t4] + (size_t)kc*128;
        uint32_t tb = stb + t4*16384;
#pragma unroll
        for (int i = 0; i < 4; i++) {
            int q = tid + i*256;
            int r = q >> 3, sc = q & 7;
            cpa16(tb + SWZ(r*128 + sc*16), src + (size_t)r*(size_t)K*2 + sc*16);
        }
    }
    asm volatile("cp.async.commit_group;" ::: "memory");
}

__global__ __launch_bounds__(256, 1) void k_mma_gemm(
    const __nv_bfloat16* __restrict__ Ah, const __nv_bfloat16* __restrict__ Al,
    const __nv_bfloat16* __restrict__ Bh, const __nv_bfloat16* __restrict__ Bl,
    const float* __restrict__ bias,
    float* __restrict__ Cf,
    __nv_bfloat16* __restrict__ Chh, __nv_bfloat16* __restrict__ Chl,
    int ldc, int K, int relu, int outBf,
    size_t sA, size_t sB, size_t sBias, size_t sC)
{
    extern __shared__ char dsm[];
    const int z = blockIdx.z;
    Ah += (size_t)z*sA;  Al += (size_t)z*sA;
    Bh += (size_t)z*sB;  Bl += (size_t)z*sB;
    bias += (size_t)z*sBias;

    const int tid = threadIdx.x;
    const int wid = tid >> 5, lane = tid & 31;
    const int row0 = blockIdx.y << 7;
    const int col0 = blockIdx.x << 7;
    const int nch = K >> 6;

    uint32_t sb = s2u(dsm);
    sb = (sb + 1023u) & ~1023u;

    const char* A0 = (const char*)(Ah + (size_t)row0*K);
    const char* A1 = (const char*)(Al + (size_t)row0*K);
    const char* B0 = (const char*)(Bh + (size_t)col0*K);
    const char* B1 = (const char*)(Bl + (size_t)col0*K);

    const int wm = (wid >> 1) * 32;
    const int wn = (wid & 1) * 64;
    const int gq8 = lane >> 3, lr = lane & 7;
    const int a_row = wm + lr + ((gq8 & 1) << 3);
    const int a_cb  = (gq8 >> 1) << 4;
    const int b_row = wn + lr + ((gq8 >> 1) << 3);
    const int b_cb  = (gq8 & 1) << 4;

    float acc[2][8][4];
#pragma unroll
    for (int mt = 0; mt < 2; mt++)
#pragma unroll
        for (int nt = 0; nt < 8; nt++)
#pragma unroll
            for (int j = 0; j < 4; j++) acc[mt][nt][j] = 0.f;

    load_stage(sb, 0, 0, A0, A1, B0, B1, K, tid);
    if (nch > 1) load_stage(sb, 1, 1, A0, A1, B0, B1, K, tid);

    int sidx = 0;
    for (int kc = 0; kc < nch; kc++) {
        if (kc + 1 < nch)
            asm volatile("cp.async.wait_group 1;" ::: "memory");
        else
            asm volatile("cp.async.wait_group 0;" ::: "memory");
        __syncthreads();
        if (kc + 2 < nch) {
            int ls = sidx + 2; if (ls >= 3) ls -= 3;
            load_stage(sb, ls, kc + 2, A0, A1, B0, B1, K, tid);
        }
        const uint32_t stb = sb + sidx*65536;
#pragma unroll
        for (int ks = 0; ks < 4; ks++) {
            const int k0b = ks * 32;
            uint32_t ah[2][4], al[2][4];
#pragma unroll
            for (int mt = 0; mt < 2; mt++) {
                uint32_t off = SWZ((uint32_t)((a_row + mt*16)*128 + (a_cb + k0b)));
                ldsm4(ah[mt], stb + off);
                ldsm4(al[mt], stb + 16384 + off);
            }
            uint32_t bh[4][4], bl[4][4];
#pragma unroll
            for (int gg = 0; gg < 4; gg++) {
                uint32_t off = SWZ((uint32_t)((b_row + gg*16)*128 + (b_cb + k0b)));
                ldsm4(bh[gg], stb + 32768 + off);
                ldsm4(bl[gg], stb + 49152 + off);
            }
#pragma unroll
            for (int mt = 0; mt < 2; mt++)
#pragma unroll
                for (int nt = 0; nt < 8; nt++) {
                    const uint32_t* bhp = &bh[nt >> 1][(nt & 1) * 2];
                    const uint32_t* blp = &bl[nt >> 1][(nt & 1) * 2];
                    mma16816(acc[mt][nt], ah[mt], bhp);
                    mma16816(acc[mt][nt], ah[mt], blp);
                    mma16816(acc[mt][nt], al[mt], bhp);
                }
        }
        sidx++; if (sidx >= 3) sidx = 0;
    }

    const int erow = row0 + wm + (lane >> 2);
    const int ecol = col0 + wn + 2*(lane & 3);
    if (outBf) {
        Chh += (size_t)z*sC; Chl += (size_t)z*sC;
#pragma unroll
        for (int mt = 0; mt < 2; mt++)
#pragma unroll
            for (int nt = 0; nt < 8; nt++) {
                int r = erow + mt*16;
                int cc = ecol + nt*8;
                float v0 = acc[mt][nt][0] + bias[cc];
                float v1 = acc[mt][nt][1] + bias[cc+1];
                float v2 = acc[mt][nt][2] + bias[cc];
                float v3 = acc[mt][nt][3] + bias[cc+1];
                if (relu) {
                    v0 = fmaxf(v0, 0.f); v1 = fmaxf(v1, 0.f);
                    v2 = fmaxf(v2, 0.f); v3 = fmaxf(v3, 0.f);
                }
                __nv_bfloat16 h0,l0,h1,l1;
                bsplit(v0,h0,l0); bsplit(v1,h1,l1);
                *(__nv_bfloat162*)&Chh[(size_t)r*ldc + cc] = __halves2bfloat162(h0,h1);
                *(__nv_bfloat162*)&Chl[(size_t)r*ldc + cc] = __halves2bfloat162(l0,l1);
                bsplit(v2,h0,l0); bsplit(v3,h1,l1);
                *(__nv_bfloat162*)&Chh[(size_t)(r+8)*ldc + cc] = __halves2bfloat162(h0,h1);
                *(__nv_bfloat162*)&Chl[(size_t)(r+8)*ldc + cc] = __halves2bfloat162(l0,l1);
            }
    } else {
        Cf += (size_t)z*sC;
#pragma unroll
        for (int mt = 0; mt < 2; mt++)
#pragma unroll
            for (int nt = 0; nt < 8; nt++) {
                int r = erow + mt*16;
                int cc = ecol + nt*8;
                float2 v0, v1;
                v0.x = acc[mt][nt][0] + bias[cc];
                v0.y = acc[mt][nt][1] + bias[cc+1];
                v1.x = acc[mt][nt][2] + bias[cc];
                v1.y = acc[mt][nt][3] + bias[cc+1];
                if (relu) {
                    v0.x = fmaxf(v0.x, 0.f); v0.y = fmaxf(v0.y, 0.f);
                    v1.x = fmaxf(v1.x, 0.f); v1.y = fmaxf(v1.y, 0.f);
                }
                *(float2*)&Cf[(size_t)r*ldc + cc]     = v0;
                *(float2*)&Cf[(size_t)(r+8)*ldc + cc] = v1;
            }
    }
}

// ---------------- persistent BiLSTM (R9: scalar FFMA, fast gates) ----------
__global__ __launch_bounds__(256) void k_lstm()
{
    const int dir = blockIdx.x >> 5;
    const int rg  = blockIdx.x & 31;
    const int j = threadIdx.x;
    const float* __restrict__ Wq = g_whhq[dir];
    const float* __restrict__ xp = g_xp[dir];
    __shared__ float hbuf[2][4][HHX];
#pragma unroll
    for (int r = 0; r < 4; r++) hbuf[0][r][j] = 0.f;
    float c[4] = {0.f, 0.f, 0.f, 0.f};
    __syncthreads();
    int p = 0;
    for (int t = 0; t < LX; t++) {
        const int tseq = dir ? (LX - 1 - t) : t;
        float a0[4] = {0,0,0,0}, a1[4] = {0,0,0,0};
        float a2[4] = {0,0,0,0}, a3[4] = {0,0,0,0};
#pragma unroll 4
        for (int k = 0; k < HHX; k++) {
            float4 w = *(const float4*)&Wq[((size_t)k*HHX + j)*4];
#pragma unroll
            for (int r = 0; r < 4; r++) {
                float hv = hbuf[p][r][k];
                a0[r] = fmaf(w.x, hv, a0[r]);
                a1[r] = fmaf(w.y, hv, a1[r]);
                a2[r] = fmaf(w.z, hv, a2[r]);
                a3[r] = fmaf(w.w, hv, a3[r]);
            }
        }
#pragma unroll
        for (int r = 0; r < 4; r++) {
            const int row = rg*4 + r;
            const size_t nidx = (size_t)row*LX + tseq;
            const float* xr = xp + nidx*(4*HHX);
            float gi = a0[r] + xr[j];
            float gf = a1[r] + xr[HHX + j];
            float gg = a2[r] + xr[2*HHX + j];
            float go = a3[r] + xr[3*HHX + j];
            float si = fsig(gi), sf = fsig(gf), so = fsig(go);
            float tg = ftanh(gg);
            c[r] = sf*c[r] + si*tg;
            float hv = so * ftanh(c[r]);
            hbuf[p ^ 1][r][j] = hv;
            g_nrep[nidx*HX + (size_t)dir*HHX + j] = hv;
        }
        __syncthreads();
        p ^= 1;
    }
}

// ------- padding row (nrep) + zero self rows of cat row N ------------------
__global__ void k_pad_zero(const float* __restrict__ pad)
{
    int j = threadIdx.x;
    if (j < HX) {
        g_nrep[(size_t)NX*HX + j] = pad[j];
        __nv_bfloat16 z = __float2bfloat16(0.f);
#pragma unroll
        for (int pp = 0; pp < 2; pp++)
#pragma unroll
            for (int d = 0; d < 2; d++) {
                g_cath[pp][d][(size_t)NX*K_SAGE + j] = z;
                g_catl[pp][d][(size_t)NX*K_SAGE + j] = z;
            }
    }
}

// ------- initial self half of cat[0] = split(node_repres[batch_nodes]) -----
__global__ void k_init_cat(const int* __restrict__ nodes)
{
    int idx = blockIdx.x * blockDim.x + threadIdx.x;
    if (idx >= NX*HX) return;
    int n = idx >> 9, cc = idx & (HX - 1);
    float v = g_nrep[(size_t)nodes[n]*HX + cc];
    __nv_bfloat16 h, l; bsplit(v, h, l);
    size_t o = (size_t)n*K_SAGE + cc;
    g_cath[0][0][o] = h; g_catl[0][0][o] = l;
    g_cath[0][1][o] = h; g_catl[0][1][o] = l;
}

// ------- gather + mean -> mean half of cat[pp]; optional len (layer 0) -----
__global__ __launch_bounds__(128) void k_gm(
    const float* __restrict__ nrepF,
    const int* __restrict__ nodes,
    const int* __restrict__ adjF, const int* __restrict__ adjB,
    int pp, int computeLen)
{
    const int n = blockIdx.x;
    const int dir = blockIdx.y;
    const int* adj = dir ? adjB : adjF;
    __nv_bfloat16* cath = g_cath[pp][dir];
    __nv_bfloat16* catl = g_catl[pp][dir];

    const int t = threadIdx.x;
    __shared__ int nb[SX];
    __shared__ float s_red[4][SX];
    __shared__ float s_inv;
    if (t < SX) nb[t] = adj[(size_t)nodes[n]*SX + t];
    if (!computeLen && t == 0) s_inv = 1.f / g_len[dir][n];
    __syncthreads();

    const int c = t * 4;
    float s0 = 0.f, s1 = 0.f, s2 = 0.f, s3 = 0.f;
    float rq[SX];
    if (computeLen) {
        // layer 0: neighbors from fp32 node_repres
#pragma unroll
        for (int q = 0; q < SX; q++) {
            const float4 v = *(const float4*)&nrepF[(size_t)nb[q]*HX + c];
            s0 += v.x; s1 += v.y; s2 += v.z; s3 += v.w;
            rq[q] = fmaxf(v.x, 0.f) + fmaxf(v.y, 0.f)
                  + fmaxf(v.z, 0.f) + fmaxf(v.w, 0.f);
        }
        const int lane = t & 31, w = t >> 5;
#pragma unroll
        for (int q = 0; q < SX; q++) {
            float x = rq[q];
#pragma unroll
            for (int o = 16; o; o >>= 1) x += __shfl_xor_sync(0xffffffffu, x, o);
            if (lane == 0) s_red[w][q] = x;
        }
        __syncthreads();
        if (t == 0) {
            float cnt = 0.f;
#pragma unroll
            for (int q = 0; q < SX; q++) {
                float tot = s_red[0][q] + s_red[1][q] + s_red[2][q] + s_red[3][q];
                if (tot > 0.f) cnt += 1.f;
            }
            g_len[dir][n] = cnt;
            s_inv = 1.f / cnt;
        }
        __syncthreads();
    } else {
        // layers >0: neighbors from cat self half (bf16 hi+lo)
#pragma unroll
        for (int q = 0; q < SX; q++) {
            size_t base = (size_t)nb[q]*K_SAGE + c;
            __nv_bfloat162 h01 = *(const __nv_bfloat162*)&cath[base];
            __nv_bfloat162 h23 = *(const __nv_bfloat162*)&cath[base+2];
            __nv_bfloat162 l01 = *(const __nv_bfloat162*)&catl[base];
            __nv_bfloat162 l23 = *(const __nv_bfloat162*)&catl[base+2];
            s0 += b2f(h01.x) + b2f(l01.x);
            s1 += b2f(h01.y) + b2f(l01.y);
            s2 += b2f(h23.x) + b2f(l23.x);
            s3 += b2f(h23.y) + b2f(l23.y);
        }
    }
    const float inv = s_inv;

    __nv_bfloat16 h0,l0,h1,l1,h2,l2,h3,l3;
    bsplit(s0*inv, h0, l0); bsplit(s1*inv, h1, l1);
    bsplit(s2*inv, h2, l2); bsplit(s3*inv, h3, l3);
    size_t o = (size_t)n*K_SAGE + HX + c;
    *(__nv_bfloat162*)&cath[o]   = __halves2bfloat162(h0, h1);
    *(__nv_bfloat162*)&cath[o+2] = __halves2bfloat162(h2, h3);
    *(__nv_bfloat162*)&catl[o]   = __halves2bfloat162(l0, l1);
    *(__nv_bfloat162*)&catl[o+2] = __halves2bfloat162(l2, l3);
}

// ---------------- finalize + pool ----------------
__global__ void k_finalize(float* __restrict__ out, int fin)
{
    int idx = blockIdx.x * blockDim.x + threadIdx.x;
    if (idx >= NX*HX) return;
    int n = idx >> 9, cc = idx & (HX - 1);
    size_t o = (size_t)n*K_SAGE + cc;
    out[(size_t)n*1024 + cc] =
        b2f(g_cath[fin][0][o]) + b2f(g_catl[fin][0][o]);
    out[(size_t)n*1024 + 512 + cc] =
        b2f(g_cath[fin][1][o]) + b2f(g_catl[fin][1][o]);
    out[(size_t)OFF_OV + idx] = g_nrep[idx];
}

__global__ void k_pool(const float* __restrict__ hid, float* __restrict__ ge)
{
    const int b = blockIdx.x;
    const int jx = threadIdx.x;
    float m = -3.402823466e38f;
    const float* base = hid + (size_t)b*LX*1024 + jx;
    for (int l = 0; l < LX; l++) m = fmaxf(m, base[(size_t)l*1024]);
    ge[(size_t)b*1024 + jx] = m;
}

// ============================ host launcher ================================
extern "C" void kernel_launch(void* const* d_in, const int* in_sizes, int n_in,
                              void* d_out, int out_size)
{
    const int*   feature_info = (const int*)d_in[0];
    const int*   batch_nodes  = (const int*)d_in[1];
    const int*   fw_adj       = (const int*)d_in[2];
    const int*   bw_adj       = (const int*)d_in[3];
    const float* W_emb        = (const float*)d_in[4];
    const float* Wih_f        = (const float*)d_in[5];
    const float* Whh_f        = (const float*)d_in[6];
    const float* bih_f        = (const float*)d_in[7];
    const float* bhh_f        = (const float*)d_in[8];
    const float* Wih_b        = (const float*)d_in[9];
    const float* Whh_b        = (const float*)d_in[10];
    const float* bih_b        = (const float*)d_in[11];
    const float* bhh_b        = (const float*)d_in[12];
    const float* padding_vec  = (const float*)d_in[13];
    const float* fw_W         = (const float*)d_in[14];
    const float* fw_b         = (const float*)d_in[15];
    const float* bw_W         = (const float*)d_in[16];
    const float* bw_b         = (const float*)d_in[17];
    float* out = (float*)d_out;

    const int DSMEM = 3*65536 + 1024;
    cudaFuncSetAttribute(k_mma_gemm, cudaFuncAttributeMaxDynamicSharedMemorySize, DSMEM);

    float *p_nrep, *p_bias, *p_sbias, *p_xp;
    __nv_bfloat16 *p_embh, *p_embl, *p_wihh, *p_wihl, *p_wh, *p_wl, *p_cath, *p_catl;
    cudaGetSymbolAddress((void**)&p_nrep, g_nrep);
    cudaGetSymbolAddress((void**)&p_bias, g_bias);
    cudaGetSymbolAddress((void**)&p_sbias,g_sbias);
    cudaGetSymbolAddress((void**)&p_xp,   g_xp);
    cudaGetSymbolAddress((void**)&p_embh, g_embh);
    cudaGetSymbolAddress((void**)&p_embl, g_embl);
    cudaGetSymbolAddress((void**)&p_wihh, g_wihh);
    cudaGetSymbolAddress((void**)&p_wihl, g_wihl);
    cudaGetSymbolAddress((void**)&p_wh,   g_wh);
    cudaGetSymbolAddress((void**)&p_wl,   g_wl);
    cudaGetSymbolAddress((void**)&p_cath, g_cath);
    cudaGetSymbolAddress((void**)&p_catl, g_catl);

    const size_t CATD = (size_t)(NX+1)*K_SAGE;   // per-dir stride
    const size_t CATP = 2*CATD;                  // per-pp stride

    // 1. embed + weight preprocessing
    k_embed<<<(NX*EMBP + 255)/256, 256>>>(feature_info, W_emb);
    k_bias<<<(LAYERSX*HX + 255)/256, 256>>>(bih_f, bhh_f, bih_b, bhh_b, fw_b, bw_b);
    k_split_wih<<<(2*1024*EMBP + 255)/256, 256>>>(Wih_f, Wih_b);
    k_split_sagew<<<(2*LAYERSX*HX*K_SAGE + 255)/256, 256>>>(fw_W, bw_W);
    k_whhq<<<(2*HHX*HHX + 255)/256, 256>>>(Whh_f, Whh_b);

    // 2. input projections, both dirs in one launch (bf16x3 mma, fp32 out)
    dim3 gxp(1024/128, NX/128, 2);
    k_mma_gemm<<<gxp, 256, DSMEM>>>(p_embh, p_embl, p_wihh, p_wihl,
                                    p_bias, p_xp, (__nv_bfloat16*)0, (__nv_bfloat16*)0,
                                    1024, EMBP, 0, 0,
                                    0, (size_t)1024*EMBP, 1024, (size_t)NX*1024);

    // 3. persistent BiLSTM -> g_nrep rows 0..N-1
    k_lstm<<<64, 256>>>();

    // 4. padding/zero rows + initial cat self half
    k_pad_zero<<<1, 512>>>(padding_vec);
    k_init_cat<<<(NX*HX + 255)/256, 256>>>(batch_nodes);

    // 5. 7 SAGE layers: k_gm fills mean half; GEMM writes next self half
    int pp = 0;
    dim3 ggm(NX, 2);
    dim3 gsage(HX/128, NX/128, 2);
    for (int l = 0; l < LAYERSX; l++) {
        k_gm<<<ggm, 128>>>(p_nrep, batch_nodes, fw_adj, bw_adj, pp, l == 0);
        k_mma_gemm<<<gsage, 256, DSMEM>>>(
            p_cath + (size_t)pp*CATP, p_catl + (size_t)pp*CATP,
            p_wh + (size_t)l*HX*K_SAGE, p_wl + (size_t)l*HX*K_SAGE,
            p_sbias + (size_t)l*HX,
            (float*)0,
            p_cath + (size_t)(pp^1)*CATP, p_catl + (size_t)(pp^1)*CATP,
            K_SAGE, K_SAGE, 1, 1,
            CATD, (size_t)LAYERSX*HX*K_SAGE, (size_t)LAYERSX*HX, CATD);
        pp ^= 1;
    }

    // 6. outputs (final hidden in cat[pp] self half)
    k_finalize<<<(NX*HX + 255)/256, 256>>>(out, pp);
    k_pool<<<BX, 1024>>>(out, out + OFF_GE);
    (void)in_sizes; (void)n_in; (void)out_size;
}

// round 13
// speedup vs baseline: 1.2568x; 1.0071x over previous
#include <cuda_runtime.h>
#include <cuda_bf16.h>
#include <math.h>
#include <stdint.h>

#define EMBX 300
#define EMBP 320
#define HX 512
#define HHX 256
#define BX 128
#define LX 128
#define NX (BX*LX)          /* 16384 */
#define SX 10
#define LAYERSX 7
#define K_SAGE 1024

#define SZ_HID (NX*2*HX)
#define OFF_GE SZ_HID
#define OFF_OV (SZ_HID + 2*BX*HX)

// ---------------- scratch (device globals) ----------------
__device__ __align__(16) __nv_bfloat16 g_embh[(size_t)NX*EMBP];
__device__ __align__(16) __nv_bfloat16 g_embl[(size_t)NX*EMBP];
__device__ __align__(16) __nv_bfloat16 g_wihh[2][(size_t)1024*EMBP];
__device__ __align__(16) __nv_bfloat16 g_wihl[2][(size_t)1024*EMBP];
__device__ __align__(16) __nv_bfloat16 g_wh[2][LAYERSX][(size_t)HX*K_SAGE];
__device__ __align__(16) __nv_bfloat16 g_wl[2][LAYERSX][(size_t)HX*K_SAGE];
// ping-pong cat: [pp][dir][(N+1) x 1024]; self cols 0-511 (GEMM-written), mean 512-1023
__device__ __align__(16) __nv_bfloat16 g_cath[2][2][(size_t)(NX+1)*K_SAGE];
__device__ __align__(16) __nv_bfloat16 g_catl[2][2][(size_t)(NX+1)*K_SAGE];
__device__ __align__(16) float g_xp[2][(size_t)NX*1024];
__device__ __align__(16) float g_nrep[(size_t)(NX+1)*HX];
__device__ __align__(16) float g_hid[2][(size_t)(NX+1)*HX];   /* fp32, for gathers */
__device__ __align__(16) float g_len[2][NX];
__device__ __align__(16) float g_bias[2][1024];
__device__ __align__(16) float g_sbias[2][LAYERSX*HX];
__device__ __align__(16) float g_whhq[2][HHX*HHX*4];

// ---------------- helpers ----------------
#define SWZ(o) ((o) ^ (((o) >> 3) & 0x70))

__device__ __forceinline__ uint32_t s2u(const void* p) {
    uint32_t a;
    asm("{ .reg .u64 t; cvta.to.shared.u64 t, %1; cvt.u32.u64 %0, t; }"
        : "=r"(a) : "l"(p));
    return a;
}
__device__ __forceinline__ void cpa16(uint32_t d, const void* g) {
    asm volatile("cp.async.cg.shared.global [%0], [%1], 16;" :: "r"(d), "l"(g));
}
__device__ __forceinline__ void ldsm4(uint32_t* r, uint32_t addr) {
    asm volatile("ldmatrix.sync.aligned.m8n8.x4.shared.b16 {%0,%1,%2,%3}, [%4];"
        : "=r"(r[0]), "=r"(r[1]), "=r"(r[2]), "=r"(r[3]) : "r"(addr));
}
__device__ __forceinline__ void mma16816(float* d, const uint32_t* a, const uint32_t* b) {
    asm volatile("mma.sync.aligned.m16n8k16.row.col.f32.bf16.bf16.f32 "
        "{%0,%1,%2,%3}, {%4,%5,%6,%7}, {%8,%9}, {%0,%1,%2,%3};"
        : "+f"(d[0]), "+f"(d[1]), "+f"(d[2]), "+f"(d[3])
        : "r"(a[0]), "r"(a[1]), "r"(a[2]), "r"(a[3]), "r"(b[0]), "r"(b[1]));
}
__device__ __forceinline__ void bsplit(float a, __nv_bfloat16& h, __nv_bfloat16& l) {
    h = __float2bfloat16(a);
    l = __float2bfloat16(a - __bfloat162float(h));
}
__device__ __forceinline__ float fsig(float x) {
    return __fdividef(1.f, 1.f + __expf(-x));
}
__device__ __forceinline__ float ftanh(float x) {
    float e = __expf(-2.f*x);
    return __fdividef(1.f - e, 1.f + e);
}
__device__ __forceinline__ float b2f(__nv_bfloat16 v) { return __bfloat162float(v); }

// ================= merged preprocessing kernel =================
#define NB_SAGEW 28672   /* 2*7*512*1024/256 */
#define NB_WIH   2560    /* 2*1024*320/256   */
#define NB_EMB   20480   /* 16384*320/256    */
#define NB_WHH   512     /* 2*256*256/256    */
#define NB_BIAS  14      /* 3584/256         */
#define NB_PREP  (NB_SAGEW + NB_WIH + NB_EMB + NB_WHH + NB_BIAS)

__global__ void k_prep(
    const int* __restrict__ feat, const float* __restrict__ Wemb,
    const float* __restrict__ Wihf, const float* __restrict__ Wihb,
    const float* __restrict__ Whhf, const float* __restrict__ Whhb,
    const float* __restrict__ bihf, const float* __restrict__ bhhf,
    const float* __restrict__ bihb, const float* __restrict__ bhhb,
    const float* __restrict__ fwW, const float* __restrict__ bwW,
    const float* __restrict__ fwb, const float* __restrict__ bwb)
{
    int b = blockIdx.x, t = threadIdx.x;
    if (b < NB_SAGEW) {
        const int per = LAYERSX*HX*K_SAGE;
        int idx = b*256 + t;
        int d = idx / per, rem = idx - d*per;
        float v = (d ? bwW : fwW)[rem];
        __nv_bfloat16 h, l; bsplit(v, h, l);
        (&g_wh[0][0][0])[(size_t)d*per + rem] = h;
        (&g_wl[0][0][0])[(size_t)d*per + rem] = l;
        return;
    }
    b -= NB_SAGEW;
    if (b < NB_WIH) {
        int idx = b*256 + t;
        int d = idx / (1024*EMBP);
        int rem = idx - d*(1024*EMBP);
        int r = rem / EMBP, e = rem - r*EMBP;
        const float* W = d ? Wihb : Wihf;
        float v = (e < EMBX) ? W[(size_t)r*EMBX + e] : 0.f;
        __nv_bfloat16 h, l; bsplit(v, h, l);
        g_wihh[d][rem] = h; g_wihl[d][rem] = l;
        return;
    }
    b -= NB_WIH;
    if (b < NB_EMB) {
        int idx = b*256 + t;
        int n = idx / EMBP, e = idx - n*EMBP;
        float v = 0.f;
        if (e < EMBX) v = Wemb[(size_t)feat[n]*EMBX + e];
        __nv_bfloat16 h, l; bsplit(v, h, l);
        g_embh[idx] = h; g_embl[idx] = l;
        return;
    }
    b -= NB_EMB;
    if (b < NB_WHH) {
        int idx = b*256 + t;
        int d = idx / (HHX*HHX);
        int rem = idx - d*(HHX*HHX);
        int k = rem / HHX, j = rem - k*HHX;
        const float* W = d ? Whhb : Whhf;
        float4 v;
        v.x = W[(size_t)(0*HHX + j)*HHX + k];
        v.y = W[(size_t)(1*HHX + j)*HHX + k];
        v.z = W[(size_t)(2*HHX + j)*HHX + k];
        v.w = W[(size_t)(3*HHX + j)*HHX + k];
        *(float4*)&g_whhq[d][(size_t)rem*4] = v;
        return;
    }
    b -= NB_WHH;
    {
        int j = b*256 + t;
        if (j < 4*HHX) {
            g_bias[0][j] = bihf[j] + bhhf[j];
            g_bias[1][j] = bihb[j] + bhhb[j];
        }
        if (j < LAYERSX*HX) {
            g_sbias[0][j] = fwb[j];
            g_sbias[1][j] = bwb[j];
        }
    }
}

// ============ mma.sync bf16x3 GEMM, dual-direction via blockIdx.z ==========
__device__ __forceinline__ void load_stage(
    uint32_t sb, int s, int kc,
    const char* A0, const char* A1, const char* B0, const char* B1,
    int K, int tid)
{
    const char* srcs[4] = { A0, A1, B0, B1 };
    uint32_t stb = sb + s*65536;
#pragma unroll
    for (int t4 = 0; t4 < 4; t4++) {
        const char* src = srcs[t4] + (size_t)kc*128;
        uint32_t tb = stb + t4*16384;
#pragma unroll
        for (int i = 0; i < 4; i++) {
            int q = tid + i*256;
            int r = q >> 3, sc = q & 7;
            cpa16(tb + SWZ(r*128 + sc*16), src + (size_t)r*(size_t)K*2 + sc*16);
        }
    }
    asm volatile("cp.async.commit_group;" ::: "memory");
}

__global__ __launch_bounds__(256, 1) void k_mma_gemm(
    const __nv_bfloat16* __restrict__ Ah, const __nv_bfloat16* __restrict__ Al,
    const __nv_bfloat16* __restrict__ Bh, const __nv_bfloat16* __restrict__ Bl,
    const float* __restrict__ bias,
    float* __restrict__ Cf,
    __nv_bfloat16* __restrict__ Chh, __nv_bfloat16* __restrict__ Chl,
    int ldcf, int K, int relu, int writeCat,
    size_t sA, size_t sB, size_t sBias, size_t sCf, size_t sCat)
{
    extern __shared__ char dsm[];
    const int z = blockIdx.z;
    Ah += (size_t)z*sA;  Al += (size_t)z*sA;
    Bh += (size_t)z*sB;  Bl += (size_t)z*sB;
    bias += (size_t)z*sBias;
    Cf += (size_t)z*sCf;

    const int tid = threadIdx.x;
    const int wid = tid >> 5, lane = tid & 31;
    const int row0 = blockIdx.y << 7;
    const int col0 = blockIdx.x << 7;
    const int nch = K >> 6;

    uint32_t sb = s2u(dsm);
    sb = (sb + 1023u) & ~1023u;

    const char* A0 = (const char*)(Ah + (size_t)row0*K);
    const char* A1 = (const char*)(Al + (size_t)row0*K);
    const char* B0 = (const char*)(Bh + (size_t)col0*K);
    const char* B1 = (const char*)(Bl + (size_t)col0*K);

    const int wm = (wid >> 1) * 32;
    const int wn = (wid & 1) * 64;
    const int gq8 = lane >> 3, lr = lane & 7;
    const int a_row = wm + lr + ((gq8 & 1) << 3);
    const int a_cb  = (gq8 >> 1) << 4;
    const int b_row = wn + lr + ((gq8 >> 1) << 3);
    const int b_cb  = (gq8 & 1) << 4;

    float acc[2][8][4];
#pragma unroll
    for (int mt = 0; mt < 2; mt++)
#pragma unroll
        for (int nt = 0; nt < 8; nt++)
#pragma unroll
            for (int j = 0; j < 4; j++) acc[mt][nt][j] = 0.f;

    load_stage(sb, 0, 0, A0, A1, B0, B1, K, tid);
    if (nch > 1) load_stage(sb, 1, 1, A0, A1, B0, B1, K, tid);

    int sidx = 0;
    for (int kc = 0; kc < nch; kc++) {
        if (kc + 1 < nch)
            asm volatile("cp.async.wait_group 1;" ::: "memory");
        else
            asm volatile("cp.async.wait_group 0;" ::: "memory");
        __syncthreads();
        if (kc + 2 < nch) {
            int ls = sidx + 2; if (ls >= 3) ls -= 3;
            load_stage(sb, ls, kc + 2, A0, A1, B0, B1, K, tid);
        }
        const uint32_t stb = sb + sidx*65536;
#pragma unroll
        for (int ks = 0; ks < 4; ks++) {
            const int k0b = ks * 32;
            uint32_t ah[2][4], al[2][4];
#pragma unroll
            for (int mt = 0; mt < 2; mt++) {
                uint32_t off = SWZ((uint32_t)((a_row + mt*16)*128 + (a_cb + k0b)));
                ldsm4(ah[mt], stb + off);
                ldsm4(al[mt], stb + 16384 + off);
            }
            uint32_t bh[4][4], bl[4][4];
#pragma unroll
            for (int gg = 0; gg < 4; gg++) {
                uint32_t off = SWZ((uint32_t)((b_row + gg*16)*128 + (b_cb + k0b)));
                ldsm4(bh[gg], stb + 32768 + off);
                ldsm4(bl[gg], stb + 49152 + off);
            }
#pragma unroll
            for (int mt = 0; mt < 2; mt++)
#pragma unroll
                for (int nt = 0; nt < 8; nt++) {
                    const uint32_t* bhp = &bh[nt >> 1][(nt & 1) * 2];
                    const uint32_t* blp = &bl[nt >> 1][(nt & 1) * 2];
                    mma16816(acc[mt][nt], ah[mt], bhp);
                    mma16816(acc[mt][nt], ah[mt], blp);
                    mma16816(acc[mt][nt], al[mt], bhp);
                }
        }
        sidx++; if (sidx >= 3) sidx = 0;
    }

    const int erow = row0 + wm + (lane >> 2);
    const int ecol = col0 + wn + 2*(lane & 3);
    if (writeCat) { Chh += (size_t)z*sCat; Chl += (size_t)z*sCat; }
#pragma unroll
    for (int mt = 0; mt < 2; mt++)
#pragma unroll
        for (int nt = 0; nt < 8; nt++) {
            int r = erow + mt*16;
            int cc = ecol + nt*8;
            float v0 = acc[mt][nt][0] + bias[cc];
            float v1 = acc[mt][nt][1] + bias[cc+1];
            float v2 = acc[mt][nt][2] + bias[cc];
            float v3 = acc[mt][nt][3] + bias[cc+1];
            if (relu) {
                v0 = fmaxf(v0, 0.f); v1 = fmaxf(v1, 0.f);
                v2 = fmaxf(v2, 0.f); v3 = fmaxf(v3, 0.f);
            }
            *(float2*)&Cf[(size_t)r*ldcf + cc]     = make_float2(v0, v1);
            *(float2*)&Cf[(size_t)(r+8)*ldcf + cc] = make_float2(v2, v3);
            if (writeCat) {
                __nv_bfloat16 h0,l0,h1,l1;
                bsplit(v0,h0,l0); bsplit(v1,h1,l1);
                *(__nv_bfloat162*)&Chh[(size_t)r*K_SAGE + cc] = __halves2bfloat162(h0,h1);
                *(__nv_bfloat162*)&Chl[(size_t)r*K_SAGE + cc] = __halves2bfloat162(l0,l1);
                bsplit(v2,h0,l0); bsplit(v3,h1,l1);
                *(__nv_bfloat162*)&Chh[(size_t)(r+8)*K_SAGE + cc] = __halves2bfloat162(h0,h1);
                *(__nv_bfloat162*)&Chl[(size_t)(r+8)*K_SAGE + cc] = __halves2bfloat162(l0,l1);
            }
        }
}

// ---------------- persistent BiLSTM (R9: scalar FFMA, fast gates) ----------
__global__ __launch_bounds__(256) void k_lstm()
{
    const int dir = blockIdx.x >> 5;
    const int rg  = blockIdx.x & 31;
    const int j = threadIdx.x;
    const float* __restrict__ Wq = g_whhq[dir];
    const float* __restrict__ xp = g_xp[dir];
    __shared__ float hbuf[2][4][HHX];
#pragma unroll
    for (int r = 0; r < 4; r++) hbuf[0][r][j] = 0.f;
    float c[4] = {0.f, 0.f, 0.f, 0.f};
    __syncthreads();
    int p = 0;
    for (int t = 0; t < LX; t++) {
        const int tseq = dir ? (LX - 1 - t) : t;
        float a0[4] = {0,0,0,0}, a1[4] = {0,0,0,0};
        float a2[4] = {0,0,0,0}, a3[4] = {0,0,0,0};
#pragma unroll 4
        for (int k = 0; k < HHX; k++) {
            float4 w = *(const float4*)&Wq[((size_t)k*HHX + j)*4];
#pragma unroll
            for (int r = 0; r < 4; r++) {
                float hv = hbuf[p][r][k];
                a0[r] = fmaf(w.x, hv, a0[r]);
                a1[r] = fmaf(w.y, hv, a1[r]);
                a2[r] = fmaf(w.z, hv, a2[r]);
                a3[r] = fmaf(w.w, hv, a3[r]);
            }
        }
#pragma unroll
        for (int r = 0; r < 4; r++) {
            const int row = rg*4 + r;
            const size_t nidx = (size_t)row*LX + tseq;
            const float* xr = xp + nidx*(4*HHX);
            float gi = a0[r] + xr[j];
            float gf = a1[r] + xr[HHX + j];
            float gg = a2[r] + xr[2*HHX + j];
            float go = a3[r] + xr[3*HHX + j];
            float si = fsig(gi), sf = fsig(gf), so = fsig(go);
            float tg = ftanh(gg);
            c[r] = sf*c[r] + si*tg;
            float hv = so * ftanh(c[r]);
            hbuf[p ^ 1][r][j] = hv;
            g_nrep[nidx*HX + (size_t)dir*HHX + j] = hv;
        }
        __syncthreads();
        p ^= 1;
    }
}

// ------ init: pad nrep row N, zero hid row N, cat[0] self = split(nrep) ----
__global__ void k_init(const int* __restrict__ nodes, const float* __restrict__ pad)
{
    int idx = blockIdx.x * blockDim.x + threadIdx.x;
    if (idx < HX) {
        g_nrep[(size_t)NX*HX + idx] = pad[idx];
        g_hid[0][(size_t)NX*HX + idx] = 0.f;
        g_hid[1][(size_t)NX*HX + idx] = 0.f;
    }
    if (idx >= NX*HX) return;
    int n = idx >> 9, cc = idx & (HX - 1);
    float v = g_nrep[(size_t)nodes[n]*HX + cc];
    __nv_bfloat16 h, l; bsplit(v, h, l);
    size_t o = (size_t)n*K_SAGE + cc;
    g_cath[0][0][o] = h; g_catl[0][0][o] = l;
    g_cath[0][1][o] = h; g_catl[0][1][o] = l;
}

// ------- gather + mean (fp32 source) -> mean half of cat[pp] ---------------
__global__ __launch_bounds__(128) void k_gm(
    const float* __restrict__ neighT, size_t sNeigh,
    const int* __restrict__ nodes,
    const int* __restrict__ adjF, const int* __restrict__ adjB,
    int pp, int computeLen)
{
    const int n = blockIdx.x;
    const int dir = blockIdx.y;
    neighT += (size_t)dir*sNeigh;
    const int* adj = dir ? adjB : adjF;
    __nv_bfloat16* cath = g_cath[pp][dir];
    __nv_bfloat16* catl = g_catl[pp][dir];

    const int t = threadIdx.x;
    __shared__ int nb[SX];
    __shared__ float s_red[4][SX];
    __shared__ float s_inv;
    if (t < SX) nb[t] = adj[(size_t)nodes[n]*SX + t];
    if (!computeLen && t == 0) s_inv = 1.f / g_len[dir][n];
    __syncthreads();

    const int c = t * 4;
    float4 s = {0.f, 0.f, 0.f, 0.f};
    float rq[SX];
#pragma unroll
    for (int q = 0; q < SX; q++) {
        const float4 v = *(const float4*)&neighT[(size_t)nb[q]*HX + c];
        s.x += v.x; s.y += v.y; s.z += v.z; s.w += v.w;
        if (computeLen) {
            rq[q] = fmaxf(v.x, 0.f) + fmaxf(v.y, 0.f)
                  + fmaxf(v.z, 0.f) + fmaxf(v.w, 0.f);
        }
    }
    if (computeLen) {
        const int lane = t & 31, w = t >> 5;
#pragma unroll
        for (int q = 0; q < SX; q++) {
            float x = rq[q];
#pragma unroll
            for (int o = 16; o; o >>= 1) x += __shfl_xor_sync(0xffffffffu, x, o);
            if (lane == 0) s_red[w][q] = x;
        }
        __syncthreads();
        if (t == 0) {
            float cnt = 0.f;
#pragma unroll
            for (int q = 0; q < SX; q++) {
                float tot = s_red[0][q] + s_red[1][q] + s_red[2][q] + s_red[3][q];
                if (tot > 0.f) cnt += 1.f;
            }
            g_len[dir][n] = cnt;
            s_inv = 1.f / cnt;
        }
        __syncthreads();
    }
    const float inv = s_inv;

    __nv_bfloat16 h0,l0,h1,l1,h2,l2,h3,l3;
    bsplit(s.x*inv, h0, l0); bsplit(s.y*inv, h1, l1);
    bsplit(s.z*inv, h2, l2); bsplit(s.w*inv, h3, l3);
    size_t o = (size_t)n*K_SAGE + HX + c;
    *(__nv_bfloat162*)&cath[o]   = __halves2bfloat162(h0, h1);
    *(__nv_bfloat162*)&cath[o+2] = __halves2bfloat162(h2, h3);
    *(__nv_bfloat162*)&catl[o]   = __halves2bfloat162(l0, l1);
    *(__nv_bfloat162*)&catl[o+2] = __halves2bfloat162(l2, l3);
}

// ---------------- fused finalize + maxpool ----------------
__global__ __launch_bounds__(1024) void k_finpool(float* __restrict__ out)
{
    const int b = blockIdx.x;
    const int t = threadIdx.x;        // 0..1023
    const int dirv = t >> 9, cc = t & 511;
    const float* hsrc = g_hid[dirv];
    float m = -3.402823466e38f;
    for (int l = 0; l < LX; l++) {
        const int n = b*LX + l;
        float v = hsrc[(size_t)n*HX + cc];
        out[(size_t)n*1024 + t] = v;
        m = fmaxf(m, v);
        if (t < 512)
            out[(size_t)OFF_OV + (size_t)n*HX + t] = g_nrep[(size_t)n*HX + t];
    }
    out[(size_t)OFF_GE + (size_t)b*1024 + t] = m;
}

// ============================ host launcher ================================
extern "C" void kernel_launch(void* const* d_in, const int* in_sizes, int n_in,
                              void* d_out, int out_size)
{
    const int*   feature_info = (const int*)d_in[0];
    const int*   batch_nodes  = (const int*)d_in[1];
    const int*   fw_adj       = (const int*)d_in[2];
    const int*   bw_adj       = (const int*)d_in[3];
    const float* W_emb        = (const float*)d_in[4];
    const float* Wih_f        = (const float*)d_in[5];
    const float* Whh_f        = (const float*)d_in[6];
    const float* bih_f        = (const float*)d_in[7];
    const float* bhh_f        = (const float*)d_in[8];
    const float* Wih_b        = (const float*)d_in[9];
    const float* Whh_b        = (const float*)d_in[10];
    const float* bih_b        = (const float*)d_in[11];
    const float* bhh_b        = (const float*)d_in[12];
    const float* padding_vec  = (const float*)d_in[13];
    const float* fw_W         = (const float*)d_in[14];
    const float* fw_b         = (const float*)d_in[15];
    const float* bw_W         = (const float*)d_in[16];
    const float* bw_b         = (const float*)d_in[17];
    float* out = (float*)d_out;

    const int DSMEM = 3*65536 + 1024;
    cudaFuncSetAttribute(k_mma_gemm, cudaFuncAttributeMaxDynamicSharedMemorySize, DSMEM);

    float *p_nrep, *p_hid, *p_bias, *p_sbias, *p_xp;
    __nv_bfloat16 *p_embh, *p_embl, *p_wihh, *p_wihl, *p_wh, *p_wl, *p_cath, *p_catl;
    cudaGetSymbolAddress((void**)&p_nrep, g_nrep);
    cudaGetSymbolAddress((void**)&p_hid,  g_hid);
    cudaGetSymbolAddress((void**)&p_bias, g_bias);
    cudaGetSymbolAddress((void**)&p_sbias,g_sbias);
    cudaGetSymbolAddress((void**)&p_xp,   g_xp);
    cudaGetSymbolAddress((void**)&p_embh, g_embh);
    cudaGetSymbolAddress((void**)&p_embl, g_embl);
    cudaGetSymbolAddress((void**)&p_wihh, g_wihh);
    cudaGetSymbolAddress((void**)&p_wihl, g_wihl);
    cudaGetSymbolAddress((void**)&p_wh,   g_wh);
    cudaGetSymbolAddress((void**)&p_wl,   g_wl);
    cudaGetSymbolAddress((void**)&p_cath, g_cath);
    cudaGetSymbolAddress((void**)&p_catl, g_catl);

    const size_t CATD = (size_t)(NX+1)*K_SAGE;   // per-dir stride
    const size_t CATP = 2*CATD;                  // per-pp stride
    const size_t HIDD = (size_t)(NX+1)*HX;       // per-dir hid stride

    // 1. merged preprocessing (weights split, embed, whhq, biases)
    k_prep<<<NB_PREP, 256>>>(feature_info, W_emb, Wih_f, Wih_b, Whh_f, Whh_b,
                             bih_f, bhh_f, bih_b, bhh_b, fw_W, bw_W, fw_b, bw_b);

    // 2. input projections, both dirs (bf16x3 mma, fp32 out only)
    dim3 gxp(1024/128, NX/128, 2);
    k_mma_gemm<<<gxp, 256, DSMEM>>>(p_embh, p_embl, p_wihh, p_wihl,
                                    p_bias, p_xp, (__nv_bfloat16*)0, (__nv_bfloat16*)0,
                                    1024, EMBP, 0, 0,
                                    0, (size_t)1024*EMBP, 1024, (size_t)NX*1024, 0);

    // 3. persistent BiLSTM -> g_nrep rows 0..N-1
    k_lstm<<<64, 256>>>();

    // 4. padding/zero row + initial cat[0] self half
    k_init<<<(NX*HX + 255)/256, 256>>>(batch_nodes, padding_vec);

    // 5. 7 SAGE layers: k_gm fills mean half of cat[pp] (fp32 gathers);
    //    GEMM reads cat[pp], writes hid fp32 + cat[pp^1] self (bf16)
    int pp = 0;
    dim3 ggm(NX, 2);
    dim3 gsage(HX/128, NX/128, 2);
    for (int l = 0; l < LAYERSX; l++) {
        if (l == 0)
            k_gm<<<ggm, 128>>>(p_nrep, 0, batch_nodes, fw_adj, bw_adj, pp, 1);
        else
            k_gm<<<ggm, 128>>>(p_hid, HIDD, batch_nodes, fw_adj, bw_adj, pp, 0);
        k_mma_gemm<<<gsage, 256, DSMEM>>>(
            p_cath + (size_t)pp*CATP, p_catl + (size_t)pp*CATP,
            p_wh + (size_t)l*HX*K_SAGE, p_wl + (size_t)l*HX*K_SAGE,
            p_sbias + (size_t)l*HX,
            p_hid,
            p_cath + (size_t)(pp^1)*CATP, p_catl + (size_t)(pp^1)*CATP,
            HX, K_SAGE, 1, 1,
            CATD, (size_t)LAYERSX*HX*K_SAGE, (size_t)LAYERSX*HX, HIDD, CATD);
        pp ^= 1;
    }

    // 6. fused finalize + pool
    k_finpool<<<BX, 1024>>>(out);
    (void)in_sizes; (void)n_in; (void)out_size;
}